// round 13
// baseline (speedup 1.0000x reference)
#include <cuda_runtime.h>
#include <cstdint>
#include <cstddef>

// Problem constants
#define B_TOT   8192
#define D_IN    400
#define D_OUT   100
#define QD      10
#define NB      8            // batches per CTA (one warp each)
#define KC      25           // K chunk size
#define NCHUNK  (D_IN / KC)  // 16
#define THREADS 256

// Shared memory layout (floats)
// Mainloop: W duplicated as float2 (v,v), 128 rows x 25 k, pair-stride 27
//           (odd -> conflict-free LDS.64/STS.64), then X chunks.
#define W2_STRIDE 27                        // in float2 units
#define WS_FLOATS (128 * W2_STRIDE * 2)     // 6912
#define XS_OFF    WS_FLOATS                 // 6912
#define XS_FLOATS (NB * KC * QD)            // 2000
// QR phase (after mainloop barrier, regions reused):
//   per-warp scratch 400 floats at [warp*400): v1[100], t[100], m[100]
//   staging 1000 floats/warp at [3200 + warp*1000)
#define SCR_SIZE  400
#define STG_OFF   3200
#define SMEM_FLOATS (STG_OFF + NB * (D_OUT * QD))   // 11200 floats = 44.8 KB

typedef unsigned long long u64;

__device__ __forceinline__ void ffma2(u64 &d, u64 a, u64 b) {
    // packed fp32x2 FMA (sm_100+): d = a*b + d  (two fp32 lanes)
    asm("fma.rn.f32x2 %0, %1, %2, %0;" : "+l"(d) : "l"(a), "l"(b));
}
__device__ __forceinline__ void unpack2(u64 v, float &lo, float &hi) {
    asm("mov.b64 {%0, %1}, %2;" : "=f"(lo), "=f"(hi) : "l"(v));
}

__global__ void __launch_bounds__(THREADS, 3)
proj_qr_kernel(const float* __restrict__ gX,
               const float* __restrict__ gW,
               float* __restrict__ gOut)
{
    __shared__ float sm[SMEM_FLOATS];

    const int tid  = threadIdx.x;
    const int lane = tid & 31;
    const int warp = tid >> 5;          // warp == local batch index (0..7)
    const int b0   = blockIdx.x * NB;

    // ------------------------------------------------------------------
    // Phase 1: GEMM  Y[b] = W @ X[b].  Warp owns one batch; lane owns
    // rows r = lane + 32*j (j=0..3); rows >= 100 stay exactly 0.
    // Accumulators: 4 rows x 5 q-pairs, packed f32x2.
    // W is stored duplicated (v,v) so both FFMA2 operands come straight
    // from LDS.64 — no pack MOVs in the inner loop.
    // ------------------------------------------------------------------
    u64 acc[4][5];
#pragma unroll
    for (int j = 0; j < 4; ++j)
#pragma unroll
        for (int p = 0; p < 5; ++p) acc[j][p] = 0ull;

    float2* w2 = reinterpret_cast<float2*>(sm);
    const float* Xc = sm + XS_OFF + warp * (KC * QD);

    for (int chunk = 0; chunk < NCHUNK; ++chunk) {
        const int k0 = chunk * KC;
        __syncthreads();   // previous chunk's smem reads done

        // W chunk (duplicated): w2[o*27 + i] = (W[o,k0+i], W[o,k0+i]).
        // Consecutive tid -> consecutive i: coalesced LDG, conflict-free STS.64.
        for (int idx = tid; idx < 128 * KC; idx += THREADS) {   // 3200
            int o = idx / KC;
            int i = idx - o * KC;
            float v = (o < D_OUT) ? gW[o * D_IN + k0 + i] : 0.0f;
            w2[o * W2_STRIDE + i] = make_float2(v, v);
        }
        // X chunk: straight copy, 250 contiguous floats per batch.
        for (int idx = tid; idx < NB * KC * QD; idx += THREADS) {  // 2000
            int b = idx / (KC * QD);
            int r = idx - b * (KC * QD);
            sm[XS_OFF + idx] =
                gX[(size_t)(b0 + b) * (D_IN * QD) + (size_t)k0 * QD + r];
        }
        __syncthreads();

        const u64* wsm = reinterpret_cast<const u64*>(sm);
#pragma unroll 5
        for (int i = 0; i < KC; ++i) {
            u64 wp[4];
#pragma unroll
            for (int j = 0; j < 4; ++j)
                wp[j] = wsm[(lane + 32 * j) * W2_STRIDE + i];   // LDS.64, conflict-free

            const u64* xp = reinterpret_cast<const u64*>(Xc + i * QD); // 8B aligned
            u64 xv[5];
#pragma unroll
            for (int p = 0; p < 5; ++p) xv[p] = xp[p];   // broadcast LDS.64

#pragma unroll
            for (int j = 0; j < 4; ++j)
#pragma unroll
                for (int p = 0; p < 5; ++p)
                    ffma2(acc[j][p], wp[j], xv[p]);
        }
    }
    __syncthreads();   // all warps done with W/X smem (regions reused below)

    // Unpack Y into registers A[j][c]
    float A[4][QD];
#pragma unroll
    for (int j = 0; j < 4; ++j)
#pragma unroll
        for (int p = 0; p < 5; ++p)
            unpack2(acc[j][p], A[j][2 * p], A[j][2 * p + 1]);

    // ------------------------------------------------------------------
    // Phase 2: Householder QR (LAPACK slarfg convention) per warp.
    // Column k of A becomes v_k (zeros above diag, 1 at k, scaled tail).
    // ------------------------------------------------------------------
    const unsigned FULL = 0xffffffffu;
    float tau[QD];

#pragma unroll
    for (int k = 0; k < QD; ++k) {
        float alpha = __shfl_sync(FULL, A[0][k], k);   // row k lives in lane k, j=0
        float s = 0.0f;
#pragma unroll
        for (int j = 0; j < 4; ++j) {
            int r = lane + 32 * j;
            float v = A[j][k];
            s += (r > k) ? v * v : 0.0f;
        }
#pragma unroll
        for (int off = 16; off; off >>= 1) s += __shfl_xor_sync(FULL, s, off);

        float tk, inv;
        if (s == 0.0f) {            // zero tail -> tau = 0 (LAPACK), H = I
            tk = 0.0f; inv = 0.0f;
        } else {
            float nrm  = sqrtf(fmaf(alpha, alpha, s));
            float beta = (alpha >= 0.0f) ? -nrm : nrm;  // -sign(alpha)*||x||
            tk  = (beta - alpha) / beta;
            inv = 1.0f / (alpha - beta);
        }
        tau[k] = tk;

        // column k -> v_k  (v[k]=1, tail scaled, zeros above)
#pragma unroll
        for (int j = 0; j < 4; ++j) {
            int r = lane + 32 * j;
            float v = A[j][k];
            A[j][k] = (r == k) ? 1.0f : ((r > k) ? v * inv : 0.0f);
        }

        // trailing update: A[:,c] -= tau * (v^T A[:,c]) * v  for c > k
        float d[QD];
#pragma unroll
        for (int c = k + 1; c < QD; ++c) {
            float p = 0.0f;
#pragma unroll
            for (int j = 0; j < 4; ++j) p = fmaf(A[j][k], A[j][c], p);
            d[c] = p;
        }
#pragma unroll
        for (int off = 16; off; off >>= 1)
#pragma unroll
            for (int c = k + 1; c < QD; ++c)
                d[c] += __shfl_xor_sync(FULL, d[c], off);
#pragma unroll
        for (int c = k + 1; c < QD; ++c) {
            float w = tau[k] * d[c];
#pragma unroll
            for (int j = 0; j < 4; ++j)
                A[j][c] = fmaf(-w, A[j][k], A[j][c]);
        }
    }

    // ------------------------------------------------------------------
    // Phase 3: compact-WY Q formation.
    //   Q = H_0 H_1 ... H_9 [I;0] = [I;0] - V * (T * V1^T)
    // with T from the LARFT forward-columnwise recurrence and V1 the top
    // 10x10 (unit lower-triangular) block of V. No Qm registers, and the
    // only warp reductions are the 45 Gram dot-products of V.
    // ------------------------------------------------------------------
    float* scr = sm + warp * SCR_SIZE;   // v1[100], t[100], m[100]
    float* v1s = scr;
    float* ts  = scr + 100;
    float* ms  = scr + 200;

    // V1: rows 0..9 of V (lane c holds row c in A[0][*])
    if (lane < QD) {
#pragma unroll
        for (int i = 0; i < QD; ++i) v1s[lane * QD + i] = A[0][i];
    }
    __syncwarp();

    // Gram columns g[j] = v_j . v_k (warp-reduced), T built incrementally
    // by lane 0 (all lanes hold the reduced g after the xor butterfly).
#pragma unroll
    for (int k = 0; k < QD; ++k) {
        float g[QD];
#pragma unroll
        for (int j = 0; j < k; ++j) {
            float p = 0.0f;
#pragma unroll
            for (int jr = 0; jr < 4; ++jr) p = fmaf(A[jr][j], A[jr][k], p);
            g[j] = p;
        }
#pragma unroll
        for (int off = 16; off; off >>= 1)
#pragma unroll
            for (int j = 0; j < k; ++j)
                g[j] += __shfl_xor_sync(FULL, g[j], off);

        if (lane == 0) {
#pragma unroll
            for (int j = 0; j < k; ++j) {
                float s2 = 0.0f;
#pragma unroll
                for (int i = j; i < k; ++i)
                    s2 = fmaf(ts[j * QD + i], g[i], s2);
                ts[j * QD + k] = -tau[k] * s2;
            }
            ts[k * QD + k] = tau[k];
        }
    }
    __syncwarp();

    // M = T * V1^T  (upper-triangular in (j<=c); lanes 0..9 each build a column)
    if (lane < QD) {
        int c = lane;
#pragma unroll
        for (int j = 0; j < QD; ++j) {
            float s2 = 0.0f;
#pragma unroll
            for (int i = j; i < QD; ++i)
                if (i <= c) s2 = fmaf(ts[j * QD + i], v1s[c * QD + i], s2);
            ms[j * QD + c] = (j <= c) ? s2 : 0.0f;
        }
    }
    __syncwarp();

    // Q[r][c] = delta(r,c) - sum_j V[r][j] * M[j][c], staged to smem.
    float* stg = sm + STG_OFF + warp * (D_OUT * QD);
#pragma unroll
    for (int c = 0; c < QD; ++c) {
        float mv[QD];
#pragma unroll
        for (int j = 0; j < QD; ++j) mv[j] = ms[j * QD + c];   // broadcast LDS
#pragma unroll
        for (int jr = 0; jr < 4; ++jr) {
            int r = lane + 32 * jr;
            float q = (r == c) ? 1.0f : 0.0f;
#pragma unroll
            for (int j = 0; j < QD; ++j) q = fmaf(-A[jr][j], mv[j], q);
            if (r < D_OUT) stg[r * QD + c] = q;
        }
    }
    __syncwarp();

    // Coalesced global store
    const size_t outBase = (size_t)(b0 + warp) * (D_OUT * QD);
    for (int idx = lane; idx < D_OUT * QD; idx += 32)
        gOut[outBase + idx] = stg[idx];
}

extern "C" void kernel_launch(void* const* d_in, const int* in_sizes, int n_in,
                              void* d_out, int out_size)
{
    const float* X = (const float*)d_in[0];   // (8192, 400, 10) fp32
    const float* W = (const float*)d_in[1];   // (100, 400) fp32
    float* out = (float*)d_out;               // (8192, 100, 10) fp32
    (void)in_sizes; (void)n_in; (void)out_size;

    proj_qr_kernel<<<B_TOT / NB, THREADS>>>(X, W, out);
}